// round 10
// baseline (speedup 1.0000x reference)
#include <cuda_runtime.h>
#include <math.h>

// Problem constants (B=2, N=4096, C=256, K=64; hidden = 256, out = 256)
#define PB 2
#define PN 4096
#define PC 256
#define PK 64
#define NS 8                 // split-K over points: 8 segments of 512 points
#define SEG (PN / NS)        // 512 points per segment
#define MB 4                 // bk-rows per MLP CTA
#define MCTAS (PB * PK / MB) // 32

// Scratch: partial maxima [B*K][NS][64 float4] and counts [B*K][NS]
__device__ float4 g_part4[PB * PK * NS * 64];
__device__ int    g_cnt[PB * PK * NS];

// ---------------- Kernel A: segment pooling ----------------
__global__ __launch_bounds__(256)
void pool_partial_kernel(const float* __restrict__ points,   // (B, N, 3)
                         const float* __restrict__ feats,    // (B, N, C)
                         const float* __restrict__ props)    // (B, K, 7)
{
    const int blk = blockIdx.x;      // bk * NS + s
    const int bk  = blk >> 3;
    const int s   = blk & (NS - 1);
    const int b   = bk / PK;
    const int t   = threadIdx.x;
    const int q   = t & 63;          // channel quad
    const int sl  = t >> 6;          // slice 0..3

    __shared__ int    s_idx[SEG];
    __shared__ int    s_count;
    __shared__ float  s_box[6];
    __shared__ float4 s_part[256];

    if (t == 0) s_count = 0;
    if (t < 3) {
        float c = props[bk * 7 + t];
        float h = props[bk * 7 + 3 + t] * 0.5f;
        s_box[t]     = c - h;
        s_box[t + 3] = c + h;
    }
    __syncthreads();

    const float lx = s_box[0], ly = s_box[1], lz = s_box[2];
    const float hx = s_box[3], hy = s_box[4], hz = s_box[5];

    const float* pb = points + (size_t)b * PN * 3;
    const int n0 = s * SEG;
    #pragma unroll
    for (int it = 0; it < SEG / 256; it++) {
        int n = n0 + it * 256 + t;
        float px = pb[n * 3 + 0];
        float py = pb[n * 3 + 1];
        float pz = pb[n * 3 + 2];
        bool inside = (px > lx) & (px < hx) &
                      (py > ly) & (py < hy) &
                      (pz > lz) & (pz < hz);
        if (inside) {
            int pos = atomicAdd(&s_count, 1);
            s_idx[pos] = n;
        }
    }
    __syncthreads();
    const int cnt = s_count;

    const float4* fb4 = (const float4*)(feats + (size_t)b * PN * PC);
    float4 acc = make_float4(-INFINITY, -INFINITY, -INFINITY, -INFINITY);
    {
        int i = sl;
        for (; i + 12 < cnt; i += 16) {
            int i0 = s_idx[i + 0];
            int i1 = s_idx[i + 4];
            int i2 = s_idx[i + 8];
            int i3 = s_idx[i + 12];
            float4 v0 = fb4[(size_t)i0 * 64 + q];
            float4 v1 = fb4[(size_t)i1 * 64 + q];
            float4 v2 = fb4[(size_t)i2 * 64 + q];
            float4 v3 = fb4[(size_t)i3 * 64 + q];
            acc.x = fmaxf(acc.x, fmaxf(fmaxf(v0.x, v1.x), fmaxf(v2.x, v3.x)));
            acc.y = fmaxf(acc.y, fmaxf(fmaxf(v0.y, v1.y), fmaxf(v2.y, v3.y)));
            acc.z = fmaxf(acc.z, fmaxf(fmaxf(v0.z, v1.z), fmaxf(v2.z, v3.z)));
            acc.w = fmaxf(acc.w, fmaxf(fmaxf(v0.w, v1.w), fmaxf(v2.w, v3.w)));
        }
        for (; i < cnt; i += 4) {
            float4 v = fb4[(size_t)s_idx[i] * 64 + q];
            acc.x = fmaxf(acc.x, v.x);
            acc.y = fmaxf(acc.y, v.y);
            acc.z = fmaxf(acc.z, v.z);
            acc.w = fmaxf(acc.w, v.w);
        }
    }
    s_part[t] = acc;
    __syncthreads();

    if (t < 64) {
        float4 a  = s_part[t];
        float4 c1 = s_part[64 + t];
        float4 c2 = s_part[128 + t];
        float4 c3 = s_part[192 + t];
        a.x = fmaxf(fmaxf(a.x, c1.x), fmaxf(c2.x, c3.x));
        a.y = fmaxf(fmaxf(a.y, c1.y), fmaxf(c2.y, c3.y));
        a.z = fmaxf(fmaxf(a.z, c1.z), fmaxf(c2.z, c3.z));
        a.w = fmaxf(fmaxf(a.w, c1.w), fmaxf(c2.w, c3.w));
        g_part4[(size_t)blk * 64 + t] = a;
    }
    if (t == 0) g_cnt[blk] = cnt;
}

// ---------------- Kernel B: reduce partials + row-batched MLP ----------------
__global__ __launch_bounds__(1024)
void mlp_kernel(const float* __restrict__ W1,   // (C, 256)
                const float* __restrict__ b1,
                const float* __restrict__ W2,   // (256, 256)
                const float* __restrict__ b2,
                float* __restrict__ out)        // (B, K, 256)
{
    const int bk0 = blockIdx.x * MB;     // first of MB rows handled here
    const int t   = threadIdx.x;
    const int q   = t & 63;              // output quad
    const int sl  = t >> 6;              // contraction slice 0..15

    __shared__ float4 s_part[2048];      // 32 KB: 2 rows' slice partials
    __shared__ float4 s_vec[MB * 64];    // MB pooled vectors
    __shared__ float4 s_h[MB * 64];      // MB hidden vectors
    __shared__ int    s_cnt[MB];

    // load MB*NS partial vectors (MB*512 float4, contiguous) coalesced
    #pragma unroll
    for (int i = t; i < MB * NS * 64; i += 1024) {
        s_part[i] = g_part4[(size_t)bk0 * (NS * 64) + i];
    }
    if (t < MB) {
        int c = 0;
        #pragma unroll
        for (int i = 0; i < NS; i++) c += g_cnt[(bk0 + t) * NS + i];
        s_cnt[t] = c;
    }
    __syncthreads();

    // fold NS=8 partials per row (256 threads: row = t>>6)
    if (t < MB * 64) {
        int row = t >> 6, qq = t & 63;
        float4 a = s_part[row * (NS * 64) + qq];
        #pragma unroll
        for (int g = 1; g < NS; g++) {
            float4 c = s_part[row * (NS * 64) + g * 64 + qq];
            a.x = fmaxf(a.x, c.x);
            a.y = fmaxf(a.y, c.y);
            a.z = fmaxf(a.z, c.z);
            a.w = fmaxf(a.w, c.w);
        }
        if (s_cnt[row] == 0) a = make_float4(0.f, 0.f, 0.f, 0.f);
        s_vec[row * 64 + qq] = a;
    }
    __syncthreads();

    // ---- layer 1: H = relu(X @ W1 + b1); each thread: 16 c's, MB rows ----
    float4 acc[MB];
    {
        #pragma unroll
        for (int r = 0; r < MB; r++) acc[r] = make_float4(0.f, 0.f, 0.f, 0.f);
        const float4* W1_4 = (const float4*)W1;
        const float*  vecf = (const float*)s_vec;
        const int c0 = sl * 16;
        #pragma unroll
        for (int c = 0; c < 16; c++) {
            float4 w = W1_4[(size_t)(c0 + c) * 64 + q];
            #pragma unroll
            for (int r = 0; r < MB; r++) {
                float f = vecf[r * 256 + c0 + c];    // warp-uniform LDS
                acc[r].x = fmaf(f, w.x, acc[r].x);
                acc[r].y = fmaf(f, w.y, acc[r].y);
                acc[r].z = fmaf(f, w.z, acc[r].z);
                acc[r].w = fmaf(f, w.w, acc[r].w);
            }
        }
    }
    // reduce 16 slices: 2 rounds × 2 rows
    #pragma unroll
    for (int p = 0; p < MB / 2; p++) {
        s_part[t]        = acc[2 * p + 0];
        s_part[1024 + t] = acc[2 * p + 1];
        __syncthreads();
        if (t < 128) {
            int rr = t >> 6, qq = t & 63;
            float4 a = s_part[rr * 1024 + qq];
            #pragma unroll
            for (int g = 1; g < 16; g++) {
                float4 c = s_part[rr * 1024 + g * 64 + qq];
                a.x += c.x; a.y += c.y; a.z += c.z; a.w += c.w;
            }
            float4 bb = ((const float4*)b1)[qq];
            a.x = fmaxf(a.x + bb.x, 0.f);
            a.y = fmaxf(a.y + bb.y, 0.f);
            a.z = fmaxf(a.z + bb.z, 0.f);
            a.w = fmaxf(a.w + bb.w, 0.f);
            s_h[(2 * p + rr) * 64 + qq] = a;
        }
        __syncthreads();
    }

    // ---- layer 2: out = relu(H @ W2 + b2) ----
    {
        #pragma unroll
        for (int r = 0; r < MB; r++) acc[r] = make_float4(0.f, 0.f, 0.f, 0.f);
        const float4* W2_4 = (const float4*)W2;
        const float*  hf = (const float*)s_h;
        const int c0 = sl * 16;
        #pragma unroll
        for (int c = 0; c < 16; c++) {
            float4 w = W2_4[(size_t)(c0 + c) * 64 + q];
            #pragma unroll
            for (int r = 0; r < MB; r++) {
                float f = hf[r * 256 + c0 + c];
                acc[r].x = fmaf(f, w.x, acc[r].x);
                acc[r].y = fmaf(f, w.y, acc[r].y);
                acc[r].z = fmaf(f, w.z, acc[r].z);
                acc[r].w = fmaf(f, w.w, acc[r].w);
            }
        }
    }
    #pragma unroll
    for (int p = 0; p < MB / 2; p++) {
        s_part[t]        = acc[2 * p + 0];
        s_part[1024 + t] = acc[2 * p + 1];
        __syncthreads();
        if (t < 128) {
            int rr = t >> 6, qq = t & 63;
            float4 a = s_part[rr * 1024 + qq];
            #pragma unroll
            for (int g = 1; g < 16; g++) {
                float4 c = s_part[rr * 1024 + g * 64 + qq];
                a.x += c.x; a.y += c.y; a.z += c.z; a.w += c.w;
            }
            float4 bb = ((const float4*)b2)[qq];
            a.x = fmaxf(a.x + bb.x, 0.f);
            a.y = fmaxf(a.y + bb.y, 0.f);
            a.z = fmaxf(a.z + bb.z, 0.f);
            a.w = fmaxf(a.w + bb.w, 0.f);
            ((float4*)out)[(size_t)(bk0 + 2 * p + rr) * 64 + qq] = a;
        }
        __syncthreads();
    }
}

extern "C" void kernel_launch(void* const* d_in, const int* in_sizes, int n_in,
                              void* d_out, int out_size)
{
    const float* points = (const float*)d_in[0];   // (B, N, 3)
    const float* feats  = (const float*)d_in[1];   // (B, N, C)
    const float* props  = (const float*)d_in[2];   // (B, K, 7)
    const float* W1     = (const float*)d_in[3];   // (C, 256)
    const float* b1     = (const float*)d_in[4];   // (256)
    const float* W2     = (const float*)d_in[5];   // (256, 256)
    const float* b2     = (const float*)d_in[6];   // (256)
    float*       out    = (float*)d_out;           // (B, K, 256)

    pool_partial_kernel<<<PB * PK * NS, 256>>>(points, feats, props);
    mlp_kernel<<<MCTAS, 1024>>>(W1, b1, W2, b2, out);
}